// round 3
// baseline (speedup 1.0000x reference)
#include <cuda_runtime.h>

// Problem constants
#define B_   4
#define T_   2048
#define D_   768
#define H_   12
#define DH_  64
#define M_   (B_ * T_)     // 8192 rows

// Scratch (allocation-free: __device__ globals)
__device__ float g_q[B_ * H_ * T_ * DH_];   // [B,H,T,Dh]
__device__ float g_k[B_ * H_ * T_ * DH_];
__device__ float g_v[B_ * H_ * T_ * DH_];
__device__ float g_y[B_ * T_ * D_];         // [B,T,D] attention output

// ---------------------------------------------------------------------------
// SGEMM: C[M,N] = A[M,K] @ W[N,K]^T + bias  (torch Linear)
// K = N = 768, M = 8192. 128x128x8 tiles, 8x8 per-thread micro-tile.
// mode 0/1/2: A = Aext (x), out = g_q/g_k/g_v scattered to [B,H,T,Dh]
// mode 3:     A = g_y,      out = outext row-major [M,N]
// ---------------------------------------------------------------------------
__global__ __launch_bounds__(256, 2) void sgemm_nt(
    const float* __restrict__ Aext, const float* __restrict__ W,
    const float* __restrict__ bias, float* __restrict__ outext, int mode)
{
    const int K = D_;
    __shared__ float As[8][128];
    __shared__ float Bs[8][128];

    const float* A = (mode == 3) ? g_y : Aext;

    const int tid = threadIdx.x;
    const int m0  = blockIdx.y * 128;
    const int n0  = blockIdx.x * 128;
    const int tx  = tid & 15;        // 0..15  -> column block
    const int ty  = tid >> 4;        // 0..15  -> row block

    const int lr  = tid >> 1;        // 0..127 tile row for loading
    const int lk  = (tid & 1) * 4;   // 0 or 4

    float c[8][8];
    #pragma unroll
    for (int i = 0; i < 8; i++)
        #pragma unroll
        for (int j = 0; j < 8; j++) c[i][j] = 0.0f;

    const float* Ap = A + (size_t)(m0 + lr) * K + lk;
    const float* Wp = W + (size_t)(n0 + lr) * K + lk;

    for (int kk = 0; kk < K; kk += 8) {
        float4 av = *(const float4*)(Ap + kk);
        float4 wv = *(const float4*)(Wp + kk);
        As[lk + 0][lr] = av.x; As[lk + 1][lr] = av.y;
        As[lk + 2][lr] = av.z; As[lk + 3][lr] = av.w;
        Bs[lk + 0][lr] = wv.x; Bs[lk + 1][lr] = wv.y;
        Bs[lk + 2][lr] = wv.z; Bs[lk + 3][lr] = wv.w;
        __syncthreads();

        #pragma unroll
        for (int k = 0; k < 8; k++) {
            float a[8], b[8];
            *(float4*)&a[0] = *(const float4*)&As[k][ty * 8];
            *(float4*)&a[4] = *(const float4*)&As[k][ty * 8 + 4];
            *(float4*)&b[0] = *(const float4*)&Bs[k][tx * 8];
            *(float4*)&b[4] = *(const float4*)&Bs[k][tx * 8 + 4];
            #pragma unroll
            for (int i = 0; i < 8; i++)
                #pragma unroll
                for (int j = 0; j < 8; j++)
                    c[i][j] = fmaf(a[i], b[j], c[i][j]);
        }
        __syncthreads();
    }

    // Epilogue: + bias, scatter
    const int ncol = n0 + tx * 8;
    float bv[8];
    #pragma unroll
    for (int j = 0; j < 8; j++) bv[j] = bias[ncol + j];

    float* outbase;
    if      (mode == 0) outbase = g_q;
    else if (mode == 1) outbase = g_k;
    else if (mode == 2) outbase = g_v;
    else                outbase = outext;

    #pragma unroll
    for (int i = 0; i < 8; i++) {
        const int m = m0 + ty * 8 + i;
        float r[8];
        #pragma unroll
        for (int j = 0; j < 8; j++) r[j] = c[i][j] + bv[j];

        float* op;
        if (mode == 3) {
            op = outbase + (size_t)m * D_ + ncol;
        } else {
            const int b  = m / T_;
            const int t  = m % T_;
            const int h  = ncol / DH_;     // constant across the 8 cols (8 | 64)
            const int dh = ncol % DH_;
            op = outbase + (((size_t)(b * H_ + h)) * T_ + t) * DH_ + dh;
        }
        *(float4*)(op + 0) = make_float4(r[0], r[1], r[2], r[3]);
        *(float4*)(op + 4) = make_float4(r[4], r[5], r[6], r[7]);
    }
}

// ---------------------------------------------------------------------------
// Causal flash attention.
// Grid: (T/128, B*H). Block: 128 threads, 1 thread = 1 query row.
// Br=128 query rows per block, Bc=32 keys per KV tile.
// q[64], o[64] in registers; K/V tiles in smem ([T,64] layout makes each
// tile a contiguous 8KB block -> perfectly coalesced loads); raw scores /
// probs in padded smem Ps (stride 33 -> conflict-free per-thread rows).
// ---------------------------------------------------------------------------
__global__ __launch_bounds__(128, 2) void flash_attn()
{
    __shared__ float Ks[32 * 64];
    __shared__ float Vs[32 * 64];
    __shared__ float Ps[128 * 33];

    const int bh  = blockIdx.y;             // b*H + h
    const int q0  = blockIdx.x * 128;
    const int tid = threadIdx.x;
    const int row = q0 + tid;               // global query index t

    const float* Qb = g_q + (size_t)bh * T_ * DH_;
    const float* Kb = g_k + (size_t)bh * T_ * DH_;
    const float* Vb = g_v + (size_t)bh * T_ * DH_;

    float q[64];
    #pragma unroll
    for (int e = 0; e < 16; e++) {
        float4 v4 = *(const float4*)(Qb + (size_t)row * DH_ + e * 4);
        q[4 * e + 0] = v4.x; q[4 * e + 1] = v4.y;
        q[4 * e + 2] = v4.z; q[4 * e + 3] = v4.w;
    }
    float o[64];
    #pragma unroll
    for (int e = 0; e < 64; e++) o[e] = 0.0f;

    float mrow = -1e30f;
    float lrow = 0.0f;

    const int ntiles = (q0 + 128) / 32;     // causal: only j0 <= q0+127

    for (int tile = 0; tile < ntiles; tile++) {
        const int j0 = tile * 32;

        __syncthreads();   // previous tile's Vs reads done before overwrite
        #pragma unroll
        for (int r4 = 0; r4 < 4; r4++) {
            const int idx = tid + r4 * 128;            // float4 index 0..511
            ((float4*)Ks)[idx] = ((const float4*)(Kb + (size_t)j0 * DH_))[idx];
            ((float4*)Vs)[idx] = ((const float4*)(Vb + (size_t)j0 * DH_))[idx];
        }
        __syncthreads();

        // Pass 1: scores + tile max
        float mt = mrow;
        #pragma unroll 4
        for (int j = 0; j < 32; j++) {
            float a0 = 0.f, a1 = 0.f, a2 = 0.f, a3 = 0.f;
            #pragma unroll
            for (int e = 0; e < 16; e++) {
                const float4 kv = *(const float4*)(Ks + j * 64 + e * 4);
                a0 = fmaf(q[4 * e + 0], kv.x, a0);
                a1 = fmaf(q[4 * e + 1], kv.y, a1);
                a2 = fmaf(q[4 * e + 2], kv.z, a2);
                a3 = fmaf(q[4 * e + 3], kv.w, a3);
            }
            float acc = ((a0 + a1) + (a2 + a3)) * 0.125f;   // 1/sqrt(64)
            if (j0 + j > row) acc = -1e30f;                 // causal mask
            mt = fmaxf(mt, acc);
            Ps[tid * 33 + j] = acc;
        }

        // Pass 2: exponentiate + running sum
        const float scale = __expf(mrow - mt);
        float lsum = 0.0f;
        #pragma unroll 4
        for (int j = 0; j < 32; j++) {
            const float p = __expf(Ps[tid * 33 + j] - mt);
            Ps[tid * 33 + j] = p;
            lsum += p;
        }
        mrow = mt;
        lrow = lrow * scale + lsum;

        #pragma unroll
        for (int e = 0; e < 64; e++) o[e] *= scale;

        // Pass 3: O += P @ V
        #pragma unroll 2
        for (int j = 0; j < 32; j++) {
            const float pj = Ps[tid * 33 + j];
            #pragma unroll
            for (int e = 0; e < 16; e++) {
                const float4 vv = *(const float4*)(Vs + j * 64 + e * 4);
                o[4 * e + 0] = fmaf(pj, vv.x, o[4 * e + 0]);
                o[4 * e + 1] = fmaf(pj, vv.y, o[4 * e + 1]);
                o[4 * e + 2] = fmaf(pj, vv.z, o[4 * e + 2]);
                o[4 * e + 3] = fmaf(pj, vv.w, o[4 * e + 3]);
            }
        }
    }

    // Write y[b, t, h*64 + e] = o / l
    const int b = bh / H_;
    const int h = bh % H_;
    const float inv = 1.0f / lrow;
    float* yp = g_y + ((size_t)(b * T_ + row)) * D_ + h * DH_;
    #pragma unroll
    for (int e = 0; e < 16; e++) {
        *(float4*)(yp + e * 4) = make_float4(o[4 * e + 0] * inv, o[4 * e + 1] * inv,
                                             o[4 * e + 2] * inv, o[4 * e + 3] * inv);
    }
}

// ---------------------------------------------------------------------------
// Launch. Inputs (metadata order): x, Wq, bq, Wk, bk, Wv, bv, Wp, bp
// ---------------------------------------------------------------------------
extern "C" void kernel_launch(void* const* d_in, const int* in_sizes, int n_in,
                              void* d_out, int out_size)
{
    (void)in_sizes; (void)n_in; (void)out_size;
    const float* x  = (const float*)d_in[0];
    const float* Wq = (const float*)d_in[1];
    const float* bq = (const float*)d_in[2];
    const float* Wk = (const float*)d_in[3];
    const float* bk = (const float*)d_in[4];
    const float* Wv = (const float*)d_in[5];
    const float* bv = (const float*)d_in[6];
    const float* Wp = (const float*)d_in[7];
    const float* bp = (const float*)d_in[8];
    float* out = (float*)d_out;

    dim3 gemm_grid(D_ / 128, M_ / 128);   // (6, 64)
    dim3 gemm_block(256);

    sgemm_nt<<<gemm_grid, gemm_block>>>(x, Wq, bq, nullptr, 0);
    sgemm_nt<<<gemm_grid, gemm_block>>>(x, Wk, bk, nullptr, 1);
    sgemm_nt<<<gemm_grid, gemm_block>>>(x, Wv, bv, nullptr, 2);

    dim3 attn_grid(T_ / 128, B_ * H_);    // (16, 48)
    flash_attn<<<attn_grid, 128>>>();

    sgemm_nt<<<gemm_grid, gemm_block>>>(nullptr, Wp, bp, out, 3);
}

// round 5
// speedup vs baseline: 1.4957x; 1.4957x over previous
#include <cuda_runtime.h>
#include <cstdint>

// Problem constants
#define B_   4
#define T_   2048
#define D_   768
#define H_   12
#define DH_  64
#define M_   (B_ * T_)     // 8192 rows

// Scratch (allocation-free: __device__ globals)
__device__ float g_q[B_ * H_ * T_ * DH_];   // [B,H,T,Dh]
__device__ float g_k[B_ * H_ * T_ * DH_];
__device__ float g_v[B_ * H_ * T_ * DH_];
__device__ float g_y[B_ * T_ * D_];         // [B,T,D] attention output

__device__ __forceinline__ uint32_t tf32_rna(float x) {
    uint32_t y;
    asm("cvt.rna.tf32.f32 %0, %1;" : "=r"(y) : "f"(x));
    return y;
}

__device__ __forceinline__ void mma_tf32(float d[4], const uint32_t a[4],
                                         const uint32_t b[2]) {
    asm volatile(
        "mma.sync.aligned.m16n8k8.row.col.f32.tf32.tf32.f32 "
        "{%0,%1,%2,%3}, {%4,%5,%6,%7}, {%8,%9}, {%0,%1,%2,%3};"
        : "+f"(d[0]), "+f"(d[1]), "+f"(d[2]), "+f"(d[3])
        : "r"(a[0]), "r"(a[1]), "r"(a[2]), "r"(a[3]), "r"(b[0]), "r"(b[1]));
}

// ---------------------------------------------------------------------------
// TF32 mma.sync GEMM: C[M,N] = A[M,K] @ W[N,K]^T + bias  (torch Linear)
// K = N = 768, M = 8192. CTA 256 thr (8 warps), tile 128x128, warp tile 64x32
// (4x4 grid of m16n8k8). smem tiles [128][36] (pad 4 -> conflict-free frags),
// double-buffered, K chunks of 32 floats, one __syncthreads per chunk.
// mode 0/1/2: A = x, out scattered to g_q/g_k/g_v [B,H,T,Dh]
// mode 3:     A = g_y, out = outext row-major [M,N]
// ---------------------------------------------------------------------------
#define KC        32
#define LDT       36                      // padded row stride (floats)
#define TILE_W    (128 * LDT)             // 4608 words per 128x32 tile
#define BUF_W     (2 * TILE_W)            // A + W per buffer
#define NITER     (D_ / KC)               // 24
#define GEMM_SMEM (2 * BUF_W * 4)         // 73728 bytes

__global__ __launch_bounds__(256, 1) void gemm_tf32(
    const float* __restrict__ Aext, const float* __restrict__ W,
    const float* __restrict__ bias, float* __restrict__ outext, int mode)
{
    extern __shared__ uint32_t sm[];      // tf32-converted values

    const int tid  = threadIdx.x;
    const int wid  = tid >> 5;
    const int lane = tid & 31;
    const int lr   = lane >> 2;           // 0..7
    const int lc   = lane & 3;            // 0..3
    const int warp_m = wid >> 2;          // 0..1 (64 rows each)
    const int warp_n = wid & 3;           // 0..3 (32 cols each)
    const int m0 = blockIdx.y * 128;
    const int n0 = blockIdx.x * 128;

    const float* A = (mode == 3) ? g_y : Aext;
    const float* Ap = A + (size_t)m0 * D_;
    const float* Wp = W + (size_t)n0 * D_;

    float d[4][4][4];
    #pragma unroll
    for (int mi = 0; mi < 4; mi++)
        #pragma unroll
        for (int ni = 0; ni < 4; ni++)
            #pragma unroll
            for (int r = 0; r < 4; r++) d[mi][ni][r] = 0.0f;

    // staging registers: 4 float4 of A, 4 float4 of W per iteration
    float4 ra[4], rw[4];

    // load tile 'it' (K offset it*KC) into registers
    auto load_tile = [&](int it) {
        const int kk = it * KC;
        #pragma unroll
        for (int i = 0; i < 4; i++) {
            const int f   = tid + i * 256;      // 0..1023
            const int row = f >> 3;
            const int c4  = f & 7;
            const size_t goff = (size_t)row * D_ + kk + c4 * 4;
            ra[i] = *(const float4*)(Ap + goff);
            rw[i] = *(const float4*)(Wp + goff);
        }
    };
    // store staged registers (tf32-converted) into buffer b
    auto store_tile = [&](int b) {
        uint32_t* As = sm + b * BUF_W;
        uint32_t* Ws = As + TILE_W;
        #pragma unroll
        for (int i = 0; i < 4; i++) {
            const int f   = tid + i * 256;
            const int row = f >> 3;
            const int c4  = f & 7;
            const int off = row * LDT + c4 * 4;
            uint32_t a0 = tf32_rna(ra[i].x), a1 = tf32_rna(ra[i].y),
                     a2 = tf32_rna(ra[i].z), a3 = tf32_rna(ra[i].w);
            uint32_t w0 = tf32_rna(rw[i].x), w1 = tf32_rna(rw[i].y),
                     w2 = tf32_rna(rw[i].z), w3 = tf32_rna(rw[i].w);
            *(uint4*)(As + off) = make_uint4(a0, a1, a2, a3);
            *(uint4*)(Ws + off) = make_uint4(w0, w1, w2, w3);
        }
    };

    load_tile(0);
    store_tile(0);
    __syncthreads();

    for (int it = 0; it < NITER; ++it) {
        const int cur = it & 1;
        if (it + 1 < NITER) load_tile(it + 1);

        const uint32_t* As = sm + cur * BUF_W;
        const uint32_t* Ws = As + TILE_W;

        #pragma unroll
        for (int k0 = 0; k0 < KC; k0 += 8) {
            uint32_t a[4][4], b[4][2];
            #pragma unroll
            for (int mi = 0; mi < 4; mi++) {
                const int r = warp_m * 64 + mi * 16;
                a[mi][0] = As[(r + lr)     * LDT + k0 + lc];
                a[mi][1] = As[(r + 8 + lr) * LDT + k0 + lc];
                a[mi][2] = As[(r + lr)     * LDT + k0 + 4 + lc];
                a[mi][3] = As[(r + 8 + lr) * LDT + k0 + 4 + lc];
            }
            #pragma unroll
            for (int ni = 0; ni < 4; ni++) {
                const int n = warp_n * 32 + ni * 8;
                b[ni][0] = Ws[(n + lr) * LDT + k0 + lc];
                b[ni][1] = Ws[(n + lr) * LDT + k0 + 4 + lc];
            }
            #pragma unroll
            for (int mi = 0; mi < 4; mi++)
                #pragma unroll
                for (int ni = 0; ni < 4; ni++)
                    mma_tf32(d[mi][ni], a[mi], b[ni]);
        }

        if (it + 1 < NITER) store_tile(cur ^ 1);
        __syncthreads();
    }

    // Epilogue. Fragment C layout (m16n8k8): c0/c1 at (row, 2lc), (row, 2lc+1);
    // c2/c3 at (row+8, ...). row = lr within 16-row tile.
    #pragma unroll
    for (int ni = 0; ni < 4; ni++) {
        const int c  = n0 + warp_n * 32 + ni * 8 + 2 * lc;
        const float b0 = __ldg(bias + c);
        const float b1 = __ldg(bias + c + 1);
        #pragma unroll
        for (int mi = 0; mi < 4; mi++) {
            #pragma unroll
            for (int half = 0; half < 2; half++) {
                const int m = m0 + warp_m * 64 + mi * 16 + half * 8 + lr;
                float2 r;
                r.x = d[mi][ni][half * 2 + 0] + b0;
                r.y = d[mi][ni][half * 2 + 1] + b1;
                float* op;
                if (mode == 3) {
                    op = outext + (size_t)m * D_ + c;
                } else {
                    const int bb = m / T_;
                    const int t  = m % T_;
                    const int h  = c / DH_;    // 2-col pair never crosses a head
                    const int dh = c % DH_;
                    float* base = (mode == 0) ? g_q : (mode == 1) ? g_k : g_v;
                    op = base + (((size_t)(bb * H_ + h)) * T_ + t) * DH_ + dh;
                }
                *(float2*)op = r;
            }
        }
    }
}

// ---------------------------------------------------------------------------
// Causal flash attention (unchanged from R3 — known good).
// Grid: (T/128, B*H). Block: 128 threads, 1 thread = 1 query row.
// ---------------------------------------------------------------------------
__global__ __launch_bounds__(128, 2) void flash_attn()
{
    __shared__ float Ks[32 * 64];
    __shared__ float Vs[32 * 64];
    __shared__ float Ps[128 * 33];

    const int bh  = blockIdx.y;             // b*H + h
    const int q0  = blockIdx.x * 128;
    const int tid = threadIdx.x;
    const int row = q0 + tid;               // global query index t

    const float* Qb = g_q + (size_t)bh * T_ * DH_;
    const float* Kb = g_k + (size_t)bh * T_ * DH_;
    const float* Vb = g_v + (size_t)bh * T_ * DH_;

    float q[64];
    #pragma unroll
    for (int e = 0; e < 16; e++) {
        float4 v4 = *(const float4*)(Qb + (size_t)row * DH_ + e * 4);
        q[4 * e + 0] = v4.x; q[4 * e + 1] = v4.y;
        q[4 * e + 2] = v4.z; q[4 * e + 3] = v4.w;
    }
    float o[64];
    #pragma unroll
    for (int e = 0; e < 64; e++) o[e] = 0.0f;

    float mrow = -1e30f;
    float lrow = 0.0f;

    const int ntiles = (q0 + 128) / 32;     // causal: only j0 <= q0+127

    for (int tile = 0; tile < ntiles; tile++) {
        const int j0 = tile * 32;

        __syncthreads();   // previous tile's Vs reads done before overwrite
        #pragma unroll
        for (int r4 = 0; r4 < 4; r4++) {
            const int idx = tid + r4 * 128;            // float4 index 0..511
            ((float4*)Ks)[idx] = ((const float4*)(Kb + (size_t)j0 * DH_))[idx];
            ((float4*)Vs)[idx] = ((const float4*)(Vb + (size_t)j0 * DH_))[idx];
        }
        __syncthreads();

        // Pass 1: scores + tile max
        float mt = mrow;
        #pragma unroll 4
        for (int j = 0; j < 32; j++) {
            float a0 = 0.f, a1 = 0.f, a2 = 0.f, a3 = 0.f;
            #pragma unroll
            for (int e = 0; e < 16; e++) {
                const float4 kv = *(const float4*)(Ks + j * 64 + e * 4);
                a0 = fmaf(q[4 * e + 0], kv.x, a0);
                a1 = fmaf(q[4 * e + 1], kv.y, a1);
                a2 = fmaf(q[4 * e + 2], kv.z, a2);
                a3 = fmaf(q[4 * e + 3], kv.w, a3);
            }
            float acc = ((a0 + a1) + (a2 + a3)) * 0.125f;   // 1/sqrt(64)
            if (j0 + j > row) acc = -1e30f;                 // causal mask
            mt = fmaxf(mt, acc);
            Ps[tid * 33 + j] = acc;
        }

        // Pass 2: exponentiate + running sum
        const float scale = __expf(mrow - mt);
        float lsum = 0.0f;
        #pragma unroll 4
        for (int j = 0; j < 32; j++) {
            const float p = __expf(Ps[tid * 33 + j] - mt);
            Ps[tid * 33 + j] = p;
            lsum += p;
        }
        mrow = mt;
        lrow = lrow * scale + lsum;

        #pragma unroll
        for (int e = 0; e < 64; e++) o[e] *= scale;

        // Pass 3: O += P @ V
        #pragma unroll 2
        for (int j = 0; j < 32; j++) {
            const float pj = Ps[tid * 33 + j];
            #pragma unroll
            for (int e = 0; e < 16; e++) {
                const float4 vv = *(const float4*)(Vs + j * 64 + e * 4);
                o[4 * e + 0] = fmaf(pj, vv.x, o[4 * e + 0]);
                o[4 * e + 1] = fmaf(pj, vv.y, o[4 * e + 1]);
                o[4 * e + 2] = fmaf(pj, vv.z, o[4 * e + 2]);
                o[4 * e + 3] = fmaf(pj, vv.w, o[4 * e + 3]);
            }
        }
    }

    // Write y[b, t, h*64 + e] = o / l
    const int b = bh / H_;
    const int h = bh % H_;
    const float inv = 1.0f / lrow;
    float* yp = g_y + ((size_t)(b * T_ + row)) * D_ + h * DH_;
    #pragma unroll
    for (int e = 0; e < 16; e++) {
        *(float4*)(yp + e * 4) = make_float4(o[4 * e + 0] * inv, o[4 * e + 1] * inv,
                                             o[4 * e + 2] * inv, o[4 * e + 3] * inv);
    }
}

// ---------------------------------------------------------------------------
// Launch. Inputs (metadata order): x, Wq, bq, Wk, bk, Wv, bv, Wp, bp
// ---------------------------------------------------------------------------
extern "C" void kernel_launch(void* const* d_in, const int* in_sizes, int n_in,
                              void* d_out, int out_size)
{
    (void)in_sizes; (void)n_in; (void)out_size;
    const float* x  = (const float*)d_in[0];
    const float* Wq = (const float*)d_in[1];
    const float* bq = (const float*)d_in[2];
    const float* Wk = (const float*)d_in[3];
    const float* bk = (const float*)d_in[4];
    const float* Wv = (const float*)d_in[5];
    const float* bv = (const float*)d_in[6];
    const float* Wp = (const float*)d_in[7];
    const float* bp = (const float*)d_in[8];
    float* out = (float*)d_out;

    cudaFuncSetAttribute(gemm_tf32, cudaFuncAttributeMaxDynamicSharedMemorySize,
                         GEMM_SMEM);

    dim3 gemm_grid(D_ / 128, M_ / 128);   // (6, 64)
    dim3 gemm_block(256);

    gemm_tf32<<<gemm_grid, gemm_block, GEMM_SMEM>>>(x, Wq, bq, nullptr, 0);
    gemm_tf32<<<gemm_grid, gemm_block, GEMM_SMEM>>>(x, Wk, bk, nullptr, 1);
    gemm_tf32<<<gemm_grid, gemm_block, GEMM_SMEM>>>(x, Wv, bv, nullptr, 2);

    dim3 attn_grid(T_ / 128, B_ * H_);    // (16, 48)
    flash_attn<<<attn_grid, 128>>>();

    gemm_tf32<<<gemm_grid, gemm_block, GEMM_SMEM>>>(nullptr, Wp, bp, out, 3);
}

// round 6
// speedup vs baseline: 3.0415x; 2.0335x over previous
#include <cuda_runtime.h>
#include <cstdint>

// Problem constants
#define B_   4
#define T_   2048
#define D_   768
#define H_   12
#define DH_  64
#define M_   (B_ * T_)     // 8192 rows

// Scratch (allocation-free: __device__ globals)
__device__ float g_q[B_ * H_ * T_ * DH_];   // [B,H,T,Dh]
__device__ float g_k[B_ * H_ * T_ * DH_];
__device__ float g_v[B_ * H_ * T_ * DH_];
__device__ float g_y[B_ * T_ * D_];         // [B,T,D] attention output

__device__ __forceinline__ uint32_t tf32_rna(float x) {
    uint32_t y;
    asm("cvt.rna.tf32.f32 %0, %1;" : "=r"(y) : "f"(x));
    return y;
}

__device__ __forceinline__ float ex2f(float x) {
    float y;
    asm("ex2.approx.f32 %0, %1;" : "=f"(y) : "f"(x));
    return y;
}

__device__ __forceinline__ void mma_tf32(float d[4], const uint32_t a[4],
                                         const uint32_t b[2]) {
    asm volatile(
        "mma.sync.aligned.m16n8k8.row.col.f32.tf32.tf32.f32 "
        "{%0,%1,%2,%3}, {%4,%5,%6,%7}, {%8,%9}, {%0,%1,%2,%3};"
        : "+f"(d[0]), "+f"(d[1]), "+f"(d[2]), "+f"(d[3])
        : "r"(a[0]), "r"(a[1]), "r"(a[2]), "r"(a[3]), "r"(b[0]), "r"(b[1]));
}

// ---------------------------------------------------------------------------
// TF32 mma.sync GEMM (unchanged from R5 — known good).
// ---------------------------------------------------------------------------
#define KC        32
#define LDT       36
#define TILE_W    (128 * LDT)
#define BUF_W     (2 * TILE_W)
#define NITER     (D_ / KC)
#define GEMM_SMEM (2 * BUF_W * 4)

__global__ __launch_bounds__(256, 1) void gemm_tf32(
    const float* __restrict__ Aext, const float* __restrict__ W,
    const float* __restrict__ bias, float* __restrict__ outext, int mode)
{
    extern __shared__ uint32_t sm[];

    const int tid  = threadIdx.x;
    const int wid  = tid >> 5;
    const int lane = tid & 31;
    const int lr   = lane >> 2;
    const int lc   = lane & 3;
    const int warp_m = wid >> 2;
    const int warp_n = wid & 3;
    const int m0 = blockIdx.y * 128;
    const int n0 = blockIdx.x * 128;

    const float* A = (mode == 3) ? g_y : Aext;
    const float* Ap = A + (size_t)m0 * D_;
    const float* Wp = W + (size_t)n0 * D_;

    float d[4][4][4];
    #pragma unroll
    for (int mi = 0; mi < 4; mi++)
        #pragma unroll
        for (int ni = 0; ni < 4; ni++)
            #pragma unroll
            for (int r = 0; r < 4; r++) d[mi][ni][r] = 0.0f;

    float4 ra[4], rw[4];

    auto load_tile = [&](int it) {
        const int kk = it * KC;
        #pragma unroll
        for (int i = 0; i < 4; i++) {
            const int f   = tid + i * 256;
            const int row = f >> 3;
            const int c4  = f & 7;
            const size_t goff = (size_t)row * D_ + kk + c4 * 4;
            ra[i] = *(const float4*)(Ap + goff);
            rw[i] = *(const float4*)(Wp + goff);
        }
    };
    auto store_tile = [&](int b) {
        uint32_t* As = sm + b * BUF_W;
        uint32_t* Ws = As + TILE_W;
        #pragma unroll
        for (int i = 0; i < 4; i++) {
            const int f   = tid + i * 256;
            const int row = f >> 3;
            const int c4  = f & 7;
            const int off = row * LDT + c4 * 4;
            uint32_t a0 = tf32_rna(ra[i].x), a1 = tf32_rna(ra[i].y),
                     a2 = tf32_rna(ra[i].z), a3 = tf32_rna(ra[i].w);
            uint32_t w0 = tf32_rna(rw[i].x), w1 = tf32_rna(rw[i].y),
                     w2 = tf32_rna(rw[i].z), w3 = tf32_rna(rw[i].w);
            *(uint4*)(As + off) = make_uint4(a0, a1, a2, a3);
            *(uint4*)(Ws + off) = make_uint4(w0, w1, w2, w3);
        }
    };

    load_tile(0);
    store_tile(0);
    __syncthreads();

    for (int it = 0; it < NITER; ++it) {
        const int cur = it & 1;
        if (it + 1 < NITER) load_tile(it + 1);

        const uint32_t* As = sm + cur * BUF_W;
        const uint32_t* Ws = As + TILE_W;

        #pragma unroll
        for (int k0 = 0; k0 < KC; k0 += 8) {
            uint32_t a[4][4], b[4][2];
            #pragma unroll
            for (int mi = 0; mi < 4; mi++) {
                const int r = warp_m * 64 + mi * 16;
                a[mi][0] = As[(r + lr)     * LDT + k0 + lc];
                a[mi][1] = As[(r + 8 + lr) * LDT + k0 + lc];
                a[mi][2] = As[(r + lr)     * LDT + k0 + 4 + lc];
                a[mi][3] = As[(r + 8 + lr) * LDT + k0 + 4 + lc];
            }
            #pragma unroll
            for (int ni = 0; ni < 4; ni++) {
                const int n = warp_n * 32 + ni * 8;
                b[ni][0] = Ws[(n + lr) * LDT + k0 + lc];
                b[ni][1] = Ws[(n + lr) * LDT + k0 + 4 + lc];
            }
            #pragma unroll
            for (int mi = 0; mi < 4; mi++)
                #pragma unroll
                for (int ni = 0; ni < 4; ni++)
                    mma_tf32(d[mi][ni], a[mi], b[ni]);
        }

        if (it + 1 < NITER) store_tile(cur ^ 1);
        __syncthreads();
    }

    #pragma unroll
    for (int ni = 0; ni < 4; ni++) {
        const int c  = n0 + warp_n * 32 + ni * 8 + 2 * lc;
        const float b0 = __ldg(bias + c);
        const float b1 = __ldg(bias + c + 1);
        #pragma unroll
        for (int mi = 0; mi < 4; mi++) {
            #pragma unroll
            for (int half = 0; half < 2; half++) {
                const int m = m0 + warp_m * 64 + mi * 16 + half * 8 + lr;
                float2 r;
                r.x = d[mi][ni][half * 2 + 0] + b0;
                r.y = d[mi][ni][half * 2 + 1] + b1;
                float* op;
                if (mode == 3) {
                    op = outext + (size_t)m * D_ + c;
                } else {
                    const int bb = m / T_;
                    const int t  = m % T_;
                    const int h  = c / DH_;
                    const int dh = c % DH_;
                    float* base = (mode == 0) ? g_q : (mode == 1) ? g_k : g_v;
                    op = base + (((size_t)(bb * H_ + h)) * T_ + t) * DH_ + dh;
                }
                *(float2*)op = r;
            }
        }
    }
}

// ---------------------------------------------------------------------------
// Tensor-core causal flash attention.
// Grid (T/128, B*H), block 256 (8 warps). Warp w owns query rows
// q0+16w .. q0+16w+15. KV tiles of Bc=64.
// QK^T: 3xTF32 (hi/lo split of Q and K) -> fp32-accurate logits.
// Softmax fp32 (ex2.approx), P -> tf32 via per-warp smem, PV: plain tf32.
// smem words: KsHi[64*68] KsLo[64*68] Vt[64*68] Ps[8][16*68]  (87,040 B)
// ---------------------------------------------------------------------------
#define FA_LD    68                       // padded stride (words)
#define FA_KS_W  (64 * FA_LD)             // 4352 words per K/V tile plane
#define FA_PS_W  (16 * FA_LD)             // 1088 words per warp P tile
#define FA_SMEM  ((3 * FA_KS_W + 8 * FA_PS_W) * 4)   // 87,040 bytes
#define CEXP     0.1803368801111244f      // 0.125 * log2(e)

__global__ __launch_bounds__(256, 1) void flash_attn_tc()
{
    extern __shared__ uint32_t fsm[];
    uint32_t* KsHi = fsm;
    uint32_t* KsLo = fsm + FA_KS_W;
    uint32_t* Vt   = fsm + 2 * FA_KS_W;

    const int tid  = threadIdx.x;
    const int wid  = tid >> 5;
    const int lane = tid & 31;
    const int lr   = lane >> 2;           // 0..7
    const int lc   = lane & 3;            // 0..3
    uint32_t* Ps = fsm + 3 * FA_KS_W + wid * FA_PS_W;

    const int bh = blockIdx.y;
    const int q0 = blockIdx.x * 128;
    const int qr0 = q0 + wid * 16;        // warp's first query row
    const int r0 = qr0 + lr;              // fragment row (upper half)
    const int r1 = r0 + 8;                // fragment row (lower half)

    const float* Qb = g_q + (size_t)bh * T_ * DH_;
    const float* Kb = g_k + (size_t)bh * T_ * DH_;
    const float* Vb = g_v + (size_t)bh * T_ * DH_;

    // Q fragments, hi/lo tf32 split. a-frag k indices: lc, lc+4 within 8-step.
    uint32_t qhi[8][4], qlo[8][4];
    #pragma unroll
    for (int ks = 0; ks < 8; ks++) {
        float v0 = Qb[(size_t)r0 * DH_ + ks * 8 + lc];
        float v1 = Qb[(size_t)r1 * DH_ + ks * 8 + lc];
        float v2 = Qb[(size_t)r0 * DH_ + ks * 8 + lc + 4];
        float v3 = Qb[(size_t)r1 * DH_ + ks * 8 + lc + 4];
        qhi[ks][0] = tf32_rna(v0); qlo[ks][0] = tf32_rna(v0 - __uint_as_float(qhi[ks][0]));
        qhi[ks][1] = tf32_rna(v1); qlo[ks][1] = tf32_rna(v1 - __uint_as_float(qhi[ks][1]));
        qhi[ks][2] = tf32_rna(v2); qlo[ks][2] = tf32_rna(v2 - __uint_as_float(qhi[ks][2]));
        qhi[ks][3] = tf32_rna(v3); qlo[ks][3] = tf32_rna(v3 - __uint_as_float(qhi[ks][3]));
    }

    float O[8][4];
    #pragma unroll
    for (int ni = 0; ni < 8; ni++)
        #pragma unroll
        for (int r = 0; r < 4; r++) O[ni][r] = 0.0f;

    float m0r = -1e30f, m1r = -1e30f;     // running row maxima (raw logits)
    float l0 = 0.0f, l1 = 0.0f;           // per-lane partial row sums

    const int jend = q0 + 128;
    for (int j0 = 0; j0 < jend; j0 += 64) {
        // ---- cooperative K/V tile load (all warps) ----
        __syncthreads();
        {
            const float* Kg = Kb + (size_t)j0 * DH_;
            const float* Vg = Vb + (size_t)j0 * DH_;
            #pragma unroll
            for (int i = 0; i < 4; i++) {
                const int f   = tid + i * 256;      // 0..1023 float4 slots
                const int row = f >> 4;             // 0..63
                const int c4  = f & 15;             // 0..15
                float4 kv = *(const float4*)(Kg + row * DH_ + c4 * 4);
                uint32_t h0 = tf32_rna(kv.x), h1 = tf32_rna(kv.y),
                         h2 = tf32_rna(kv.z), h3 = tf32_rna(kv.w);
                uint32_t l0b = tf32_rna(kv.x - __uint_as_float(h0));
                uint32_t l1b = tf32_rna(kv.y - __uint_as_float(h1));
                uint32_t l2b = tf32_rna(kv.z - __uint_as_float(h2));
                uint32_t l3b = tf32_rna(kv.w - __uint_as_float(h3));
                const int off = row * FA_LD + c4 * 4;
                *(uint4*)(KsHi + off) = make_uint4(h0, h1, h2, h3);
                *(uint4*)(KsLo + off) = make_uint4(l0b, l1b, l2b, l3b);

                float4 vv = *(const float4*)(Vg + row * DH_ + c4 * 4);
                Vt[(c4 * 4 + 0) * FA_LD + row] = tf32_rna(vv.x);
                Vt[(c4 * 4 + 1) * FA_LD + row] = tf32_rna(vv.y);
                Vt[(c4 * 4 + 2) * FA_LD + row] = tf32_rna(vv.z);
                Vt[(c4 * 4 + 3) * FA_LD + row] = tf32_rna(vv.w);
            }
        }
        __syncthreads();

        if (j0 > qr0 + 15) continue;      // whole warp-tile above diagonal

        // ---- S = Q @ K^T (3xTF32) ----
        float S[8][4];
        #pragma unroll
        for (int ni = 0; ni < 8; ni++) {
            S[ni][0] = S[ni][1] = S[ni][2] = S[ni][3] = 0.0f;
            #pragma unroll
            for (int ks = 0; ks < 8; ks++) {
                const int boff = (ni * 8 + lr) * FA_LD + ks * 8 + lc;
                uint32_t bhv[2] = { KsHi[boff], KsHi[boff + 4] };
                uint32_t blv[2] = { KsLo[boff], KsLo[boff + 4] };
                mma_tf32(S[ni], qhi[ks], bhv);
                mma_tf32(S[ni], qlo[ks], bhv);
                mma_tf32(S[ni], qhi[ks], blv);
            }
        }

        // ---- causal mask (diagonal tiles only) ----
        if (j0 + 63 > qr0) {
            #pragma unroll
            for (int ni = 0; ni < 8; ni++) {
                const int cb = j0 + ni * 8 + 2 * lc;
                if (cb     > r0) S[ni][0] = -1e30f;
                if (cb + 1 > r0) S[ni][1] = -1e30f;
                if (cb     > r1) S[ni][2] = -1e30f;
                if (cb + 1 > r1) S[ni][3] = -1e30f;
            }
        }

        // ---- online softmax ----
        float m0n = m0r, m1n = m1r;
        #pragma unroll
        for (int ni = 0; ni < 8; ni++) {
            m0n = fmaxf(m0n, fmaxf(S[ni][0], S[ni][1]));
            m1n = fmaxf(m1n, fmaxf(S[ni][2], S[ni][3]));
        }
        m0n = fmaxf(m0n, __shfl_xor_sync(0xFFFFFFFFu, m0n, 1));
        m0n = fmaxf(m0n, __shfl_xor_sync(0xFFFFFFFFu, m0n, 2));
        m1n = fmaxf(m1n, __shfl_xor_sync(0xFFFFFFFFu, m1n, 1));
        m1n = fmaxf(m1n, __shfl_xor_sync(0xFFFFFFFFu, m1n, 2));

        const float sf0 = ex2f((m0r - m0n) * CEXP);
        const float sf1 = ex2f((m1r - m1n) * CEXP);
        m0r = m0n; m1r = m1n;
        l0 *= sf0; l1 *= sf1;
        #pragma unroll
        for (int ni = 0; ni < 8; ni++) {
            O[ni][0] *= sf0; O[ni][1] *= sf0;
            O[ni][2] *= sf1; O[ni][3] *= sf1;
        }

        const float mc0 = m0n * CEXP;
        const float mc1 = m1n * CEXP;
        #pragma unroll
        for (int ni = 0; ni < 8; ni++) {
            float p0 = ex2f(fmaf(S[ni][0], CEXP, -mc0));
            float p1 = ex2f(fmaf(S[ni][1], CEXP, -mc0));
            float p2 = ex2f(fmaf(S[ni][2], CEXP, -mc1));
            float p3 = ex2f(fmaf(S[ni][3], CEXP, -mc1));
            l0 += p0 + p1;
            l1 += p2 + p3;
            *(uint2*)(Ps + lr * FA_LD + ni * 8 + 2 * lc) =
                make_uint2(tf32_rna(p0), tf32_rna(p1));
            *(uint2*)(Ps + (lr + 8) * FA_LD + ni * 8 + 2 * lc) =
                make_uint2(tf32_rna(p2), tf32_rna(p3));
        }
        __syncwarp();

        // ---- O += P @ V ----
        #pragma unroll
        for (int ks = 0; ks < 8; ks++) {
            uint32_t a[4] = {
                Ps[lr * FA_LD + ks * 8 + lc],
                Ps[(lr + 8) * FA_LD + ks * 8 + lc],
                Ps[lr * FA_LD + ks * 8 + lc + 4],
                Ps[(lr + 8) * FA_LD + ks * 8 + lc + 4]
            };
            #pragma unroll
            for (int ni = 0; ni < 8; ni++) {
                const int voff = (ni * 8 + lr) * FA_LD + ks * 8 + lc;
                uint32_t bv[2] = { Vt[voff], Vt[voff + 4] };
                mma_tf32(O[ni], a, bv);
            }
        }
        __syncwarp();   // Ps reads done before next tile overwrites
    }

    // ---- finalize: O / l, write y[b, t, h*64 + col] ----
    l0 += __shfl_xor_sync(0xFFFFFFFFu, l0, 1);
    l0 += __shfl_xor_sync(0xFFFFFFFFu, l0, 2);
    l1 += __shfl_xor_sync(0xFFFFFFFFu, l1, 1);
    l1 += __shfl_xor_sync(0xFFFFFFFFu, l1, 2);
    const float inv0 = 1.0f / l0;
    const float inv1 = 1.0f / l1;

    const int b = bh / H_;
    const int h = bh % H_;
    float* y0 = g_y + ((size_t)(b * T_ + r0)) * D_ + h * DH_;
    float* y1 = g_y + ((size_t)(b * T_ + r1)) * D_ + h * DH_;
    #pragma unroll
    for (int ni = 0; ni < 8; ni++) {
        *(float2*)(y0 + ni * 8 + 2 * lc) = make_float2(O[ni][0] * inv0, O[ni][1] * inv0);
        *(float2*)(y1 + ni * 8 + 2 * lc) = make_float2(O[ni][2] * inv1, O[ni][3] * inv1);
    }
}

// ---------------------------------------------------------------------------
// Launch. Inputs (metadata order): x, Wq, bq, Wk, bk, Wv, bv, Wp, bp
// ---------------------------------------------------------------------------
extern "C" void kernel_launch(void* const* d_in, const int* in_sizes, int n_in,
                              void* d_out, int out_size)
{
    (void)in_sizes; (void)n_in; (void)out_size;
    const float* x  = (const float*)d_in[0];
    const float* Wq = (const float*)d_in[1];
    const float* bq = (const float*)d_in[2];
    const float* Wk = (const float*)d_in[3];
    const float* bk = (const float*)d_in[4];
    const float* Wv = (const float*)d_in[5];
    const float* bv = (const float*)d_in[6];
    const float* Wp = (const float*)d_in[7];
    const float* bp = (const float*)d_in[8];
    float* out = (float*)d_out;

    cudaFuncSetAttribute(gemm_tf32, cudaFuncAttributeMaxDynamicSharedMemorySize,
                         GEMM_SMEM);
    cudaFuncSetAttribute(flash_attn_tc, cudaFuncAttributeMaxDynamicSharedMemorySize,
                         FA_SMEM);

    dim3 gemm_grid(D_ / 128, M_ / 128);   // (6, 64)
    dim3 gemm_block(256);

    gemm_tf32<<<gemm_grid, gemm_block, GEMM_SMEM>>>(x, Wq, bq, nullptr, 0);
    gemm_tf32<<<gemm_grid, gemm_block, GEMM_SMEM>>>(x, Wk, bk, nullptr, 1);
    gemm_tf32<<<gemm_grid, gemm_block, GEMM_SMEM>>>(x, Wv, bv, nullptr, 2);

    dim3 attn_grid(T_ / 128, B_ * H_);    // (16, 48)
    flash_attn_tc<<<attn_grid, 256, FA_SMEM>>>();

    gemm_tf32<<<gemm_grid, gemm_block, GEMM_SMEM>>>(nullptr, Wp, bp, out, 3);
}

// round 7
// speedup vs baseline: 3.2823x; 1.0792x over previous
#include <cuda_runtime.h>
#include <cstdint>

// Problem constants
#define B_   4
#define T_   2048
#define D_   768
#define H_   12
#define DH_  64
#define M_   (B_ * T_)     // 8192 rows

// Scratch (allocation-free: __device__ globals)
__device__ float g_q[B_ * H_ * T_ * DH_];   // [B,H,T,Dh]
__device__ float g_k[B_ * H_ * T_ * DH_];
__device__ float g_v[B_ * H_ * T_ * DH_];
__device__ float g_y[B_ * T_ * D_];         // [B,T,D] attention output

__device__ __forceinline__ uint32_t tf32_rna(float x) {
    uint32_t y;
    asm("cvt.rna.tf32.f32 %0, %1;" : "=r"(y) : "f"(x));
    return y;
}

__device__ __forceinline__ float ex2f(float x) {
    float y;
    asm("ex2.approx.f32 %0, %1;" : "=f"(y) : "f"(x));
    return y;
}

__device__ __forceinline__ void mma_tf32(float d[4], const uint32_t a[4],
                                         const uint32_t b[2]) {
    asm volatile(
        "mma.sync.aligned.m16n8k8.row.col.f32.tf32.tf32.f32 "
        "{%0,%1,%2,%3}, {%4,%5,%6,%7}, {%8,%9}, {%0,%1,%2,%3};"
        : "+f"(d[0]), "+f"(d[1]), "+f"(d[2]), "+f"(d[3])
        : "r"(a[0]), "r"(a[1]), "r"(a[2]), "r"(a[3]), "r"(b[0]), "r"(b[1]));
}

// ---------------------------------------------------------------------------
// TF32 mma.sync GEMM (unchanged — known good, R5/R6).
// ---------------------------------------------------------------------------
#define KC        32
#define LDT       36
#define TILE_W    (128 * LDT)
#define BUF_W     (2 * TILE_W)
#define NITER     (D_ / KC)
#define GEMM_SMEM (2 * BUF_W * 4)

__global__ __launch_bounds__(256, 1) void gemm_tf32(
    const float* __restrict__ Aext, const float* __restrict__ W,
    const float* __restrict__ bias, float* __restrict__ outext, int mode)
{
    extern __shared__ uint32_t sm[];

    const int tid  = threadIdx.x;
    const int wid  = tid >> 5;
    const int lane = tid & 31;
    const int lr   = lane >> 2;
    const int lc   = lane & 3;
    const int warp_m = wid >> 2;
    const int warp_n = wid & 3;
    const int m0 = blockIdx.y * 128;
    const int n0 = blockIdx.x * 128;

    const float* A = (mode == 3) ? g_y : Aext;
    const float* Ap = A + (size_t)m0 * D_;
    const float* Wp = W + (size_t)n0 * D_;

    float d[4][4][4];
    #pragma unroll
    for (int mi = 0; mi < 4; mi++)
        #pragma unroll
        for (int ni = 0; ni < 4; ni++)
            #pragma unroll
            for (int r = 0; r < 4; r++) d[mi][ni][r] = 0.0f;

    float4 ra[4], rw[4];

    auto load_tile = [&](int it) {
        const int kk = it * KC;
        #pragma unroll
        for (int i = 0; i < 4; i++) {
            const int f   = tid + i * 256;
            const int row = f >> 3;
            const int c4  = f & 7;
            const size_t goff = (size_t)row * D_ + kk + c4 * 4;
            ra[i] = *(const float4*)(Ap + goff);
            rw[i] = *(const float4*)(Wp + goff);
        }
    };
    auto store_tile = [&](int b) {
        uint32_t* As = sm + b * BUF_W;
        uint32_t* Ws = As + TILE_W;
        #pragma unroll
        for (int i = 0; i < 4; i++) {
            const int f   = tid + i * 256;
            const int row = f >> 3;
            const int c4  = f & 7;
            const int off = row * LDT + c4 * 4;
            uint32_t a0 = tf32_rna(ra[i].x), a1 = tf32_rna(ra[i].y),
                     a2 = tf32_rna(ra[i].z), a3 = tf32_rna(ra[i].w);
            uint32_t w0 = tf32_rna(rw[i].x), w1 = tf32_rna(rw[i].y),
                     w2 = tf32_rna(rw[i].z), w3 = tf32_rna(rw[i].w);
            *(uint4*)(As + off) = make_uint4(a0, a1, a2, a3);
            *(uint4*)(Ws + off) = make_uint4(w0, w1, w2, w3);
        }
    };

    load_tile(0);
    store_tile(0);
    __syncthreads();

    for (int it = 0; it < NITER; ++it) {
        const int cur = it & 1;
        if (it + 1 < NITER) load_tile(it + 1);

        const uint32_t* As = sm + cur * BUF_W;
        const uint32_t* Ws = As + TILE_W;

        #pragma unroll
        for (int k0 = 0; k0 < KC; k0 += 8) {
            uint32_t a[4][4], b[4][2];
            #pragma unroll
            for (int mi = 0; mi < 4; mi++) {
                const int r = warp_m * 64 + mi * 16;
                a[mi][0] = As[(r + lr)     * LDT + k0 + lc];
                a[mi][1] = As[(r + 8 + lr) * LDT + k0 + lc];
                a[mi][2] = As[(r + lr)     * LDT + k0 + 4 + lc];
                a[mi][3] = As[(r + 8 + lr) * LDT + k0 + 4 + lc];
            }
            #pragma unroll
            for (int ni = 0; ni < 4; ni++) {
                const int n = warp_n * 32 + ni * 8;
                b[ni][0] = Ws[(n + lr) * LDT + k0 + lc];
                b[ni][1] = Ws[(n + lr) * LDT + k0 + 4 + lc];
            }
            #pragma unroll
            for (int mi = 0; mi < 4; mi++)
                #pragma unroll
                for (int ni = 0; ni < 4; ni++)
                    mma_tf32(d[mi][ni], a[mi], b[ni]);
        }

        if (it + 1 < NITER) store_tile(cur ^ 1);
        __syncthreads();
    }

    #pragma unroll
    for (int ni = 0; ni < 4; ni++) {
        const int c  = n0 + warp_n * 32 + ni * 8 + 2 * lc;
        const float b0 = __ldg(bias + c);
        const float b1 = __ldg(bias + c + 1);
        #pragma unroll
        for (int mi = 0; mi < 4; mi++) {
            #pragma unroll
            for (int half = 0; half < 2; half++) {
                const int m = m0 + warp_m * 64 + mi * 16 + half * 8 + lr;
                float2 r;
                r.x = d[mi][ni][half * 2 + 0] + b0;
                r.y = d[mi][ni][half * 2 + 1] + b1;
                float* op;
                if (mode == 3) {
                    op = outext + (size_t)m * D_ + c;
                } else {
                    const int bb = m / T_;
                    const int t  = m % T_;
                    const int h  = c / DH_;
                    const int dh = c % DH_;
                    float* base = (mode == 0) ? g_q : (mode == 1) ? g_k : g_v;
                    op = base + (((size_t)(bb * H_ + h)) * T_ + t) * DH_ + dh;
                }
                *(float2*)op = r;
            }
        }
    }
}

// ---------------------------------------------------------------------------
// Tensor-core causal flash attention, v2.
// Grid (T/128, B*H), block 256 (8 warps), 2 CTAs/SM. Warp w: query rows
// q0+16w..+15. KV tiles Bc=64. Plain tf32 QK^T and PV.
// smem column-pair interleave: within each 8-col group, true col c sits at
// psi(c) = ((c&3)<<1)|(c>>2)  -> fragment pairs (k=lc, k=lc+4) are adjacent,
// so every fragment read is a single LDS.64 (conflict-free with LD=72).
// smem: Ks[64][72] + Vt[64][72] + Ps[8][16][72] = 73,728 B.
// ---------------------------------------------------------------------------
#define FA_LD    72
#define FA_KS_W  (64 * FA_LD)
#define FA_PS_W  (16 * FA_LD)
#define FA_SMEM  ((2 * FA_KS_W + 8 * FA_PS_W) * 4)
#define CEXP     0.1803368801111244f      // 0.125 * log2(e)

__global__ __launch_bounds__(256, 2) void flash_attn_tc()
{
    extern __shared__ uint32_t fsm[];
    uint32_t* Ks = fsm;                   // K tile, col-pair interleaved
    uint32_t* Vt = fsm + FA_KS_W;         // V^T tile, col-pair interleaved

    const int tid  = threadIdx.x;
    const int wid  = tid >> 5;
    const int lane = tid & 31;
    const int lr   = lane >> 2;           // 0..7
    const int lc   = lane & 3;            // 0..3
    uint32_t* Ps = fsm + 2 * FA_KS_W + wid * FA_PS_W;

    const int bh = blockIdx.y;
    const int q0 = blockIdx.x * 128;
    const int qr0 = q0 + wid * 16;        // warp's first query row
    const int r0 = qr0 + lr;
    const int r1 = r0 + 8;

    const float* Qb = g_q + (size_t)bh * T_ * DH_;
    const float* Kb = g_k + (size_t)bh * T_ * DH_;
    const float* Vb = g_v + (size_t)bh * T_ * DH_;

    // Q a-fragments (plain tf32)
    uint32_t q[8][4];
    #pragma unroll
    for (int ks = 0; ks < 8; ks++) {
        q[ks][0] = tf32_rna(Qb[(size_t)r0 * DH_ + ks * 8 + lc]);
        q[ks][1] = tf32_rna(Qb[(size_t)r1 * DH_ + ks * 8 + lc]);
        q[ks][2] = tf32_rna(Qb[(size_t)r0 * DH_ + ks * 8 + lc + 4]);
        q[ks][3] = tf32_rna(Qb[(size_t)r1 * DH_ + ks * 8 + lc + 4]);
    }

    float O[8][4];
    #pragma unroll
    for (int ni = 0; ni < 8; ni++)
        #pragma unroll
        for (int r = 0; r < 4; r++) O[ni][r] = 0.0f;

    float m0r = -1e30f, m1r = -1e30f;
    float l0 = 0.0f, l1 = 0.0f;

    // P store positions (within 8-group): psi(2lc), psi(2lc)+2
    const int psi0 = (lc & 1) * 4 + (lc >> 1);

    const int jend = q0 + 128;
    for (int j0 = 0; j0 < jend; j0 += 64) {
        // ---- cooperative K/V tile load + tf32 convert + pair interleave ----
        __syncthreads();
        {
            const float* Kg = Kb + (size_t)j0 * DH_;
            const float* Vg = Vb + (size_t)j0 * DH_;
            #pragma unroll
            for (int i = 0; i < 4; i++) {
                const int f   = tid + i * 256;      // 0..1023 float4 slots
                const int row = f >> 4;             // 0..63 (key index j)
                const int c4  = f & 15;             // float4 col
                // K: cols c4*4+jj -> group (c4>>1), slot jj*2 + (c4&1)
                float4 kv = *(const float4*)(Kg + row * DH_ + c4 * 4);
                uint32_t* kb = Ks + row * FA_LD + (c4 >> 1) * 8 + (c4 & 1);
                kb[0] = tf32_rna(kv.x);
                kb[2] = tf32_rna(kv.y);
                kb[4] = tf32_rna(kv.z);
                kb[6] = tf32_rna(kv.w);
                // V^T: Vt row = dh = c4*4+jj, col = j (permuted within group)
                float4 vv = *(const float4*)(Vg + row * DH_ + c4 * 4);
                const int jperm = (row & ~7) +
                                  (((row & 3) << 1) | ((row & 7) >> 2));
                Vt[(c4 * 4 + 0) * FA_LD + jperm] = tf32_rna(vv.x);
                Vt[(c4 * 4 + 1) * FA_LD + jperm] = tf32_rna(vv.y);
                Vt[(c4 * 4 + 2) * FA_LD + jperm] = tf32_rna(vv.z);
                Vt[(c4 * 4 + 3) * FA_LD + jperm] = tf32_rna(vv.w);
            }
        }
        __syncthreads();

        if (j0 > qr0 + 15) continue;      // whole warp-tile above diagonal

        // ---- S = Q @ K^T ----
        float S[8][4];
        #pragma unroll
        for (int ni = 0; ni < 8; ni++) {
            S[ni][0] = S[ni][1] = S[ni][2] = S[ni][3] = 0.0f;
            #pragma unroll
            for (int ks = 0; ks < 8; ks++) {
                uint2 bv = *(const uint2*)(Ks + (ni * 8 + lr) * FA_LD
                                              + ks * 8 + 2 * lc);
                uint32_t b2[2] = { bv.x, bv.y };
                mma_tf32(S[ni], q[ks], b2);
            }
        }

        // ---- causal mask (diagonal tiles only) ----
        if (j0 + 63 > qr0) {
            #pragma unroll
            for (int ni = 0; ni < 8; ni++) {
                const int cb = j0 + ni * 8 + 2 * lc;
                if (cb     > r0) S[ni][0] = -1e30f;
                if (cb + 1 > r0) S[ni][1] = -1e30f;
                if (cb     > r1) S[ni][2] = -1e30f;
                if (cb + 1 > r1) S[ni][3] = -1e30f;
            }
        }

        // ---- online softmax ----
        float m0n = m0r, m1n = m1r;
        #pragma unroll
        for (int ni = 0; ni < 8; ni++) {
            m0n = fmaxf(m0n, fmaxf(S[ni][0], S[ni][1]));
            m1n = fmaxf(m1n, fmaxf(S[ni][2], S[ni][3]));
        }
        m0n = fmaxf(m0n, __shfl_xor_sync(0xFFFFFFFFu, m0n, 1));
        m0n = fmaxf(m0n, __shfl_xor_sync(0xFFFFFFFFu, m0n, 2));
        m1n = fmaxf(m1n, __shfl_xor_sync(0xFFFFFFFFu, m1n, 1));
        m1n = fmaxf(m1n, __shfl_xor_sync(0xFFFFFFFFu, m1n, 2));

        const float sf0 = ex2f((m0r - m0n) * CEXP);
        const float sf1 = ex2f((m1r - m1n) * CEXP);
        m0r = m0n; m1r = m1n;
        l0 *= sf0; l1 *= sf1;
        #pragma unroll
        for (int ni = 0; ni < 8; ni++) {
            O[ni][0] *= sf0; O[ni][1] *= sf0;
            O[ni][2] *= sf1; O[ni][3] *= sf1;
        }

        const float mc0 = m0n * CEXP;
        const float mc1 = m1n * CEXP;
        #pragma unroll
        for (int ni = 0; ni < 8; ni++) {
            float p0 = ex2f(fmaf(S[ni][0], CEXP, -mc0));
            float p1 = ex2f(fmaf(S[ni][1], CEXP, -mc0));
            float p2 = ex2f(fmaf(S[ni][2], CEXP, -mc1));
            float p3 = ex2f(fmaf(S[ni][3], CEXP, -mc1));
            l0 += p0 + p1;
            l1 += p2 + p3;
            uint32_t* pr0 = Ps + lr * FA_LD + ni * 8 + psi0;
            uint32_t* pr1 = Ps + (lr + 8) * FA_LD + ni * 8 + psi0;
            pr0[0] = tf32_rna(p0); pr0[2] = tf32_rna(p1);
            pr1[0] = tf32_rna(p2); pr1[2] = tf32_rna(p3);
        }
        __syncwarp();

        // ---- O += P @ V ----
        #pragma unroll
        for (int ks = 0; ks < 8; ks++) {
            uint2 a02 = *(const uint2*)(Ps + lr * FA_LD + ks * 8 + 2 * lc);
            uint2 a13 = *(const uint2*)(Ps + (lr + 8) * FA_LD + ks * 8 + 2 * lc);
            uint32_t a[4] = { a02.x, a13.x, a02.y, a13.y };
            #pragma unroll
            for (int ni = 0; ni < 8; ni++) {
                uint2 bv = *(const uint2*)(Vt + (ni * 8 + lr) * FA_LD
                                              + ks * 8 + 2 * lc);
                uint32_t b2[2] = { bv.x, bv.y };
                mma_tf32(O[ni], a, b2);
            }
        }
        __syncwarp();   // Ps reads done before next tile overwrites
    }

    // ---- finalize ----
    l0 += __shfl_xor_sync(0xFFFFFFFFu, l0, 1);
    l0 += __shfl_xor_sync(0xFFFFFFFFu, l0, 2);
    l1 += __shfl_xor_sync(0xFFFFFFFFu, l1, 1);
    l1 += __shfl_xor_sync(0xFFFFFFFFu, l1, 2);
    const float inv0 = 1.0f / l0;
    const float inv1 = 1.0f / l1;

    const int b = bh / H_;
    const int h = bh % H_;
    float* y0 = g_y + ((size_t)(b * T_ + r0)) * D_ + h * DH_;
    float* y1 = g_y + ((size_t)(b * T_ + r1)) * D_ + h * DH_;
    #pragma unroll
    for (int ni = 0; ni < 8; ni++) {
        *(float2*)(y0 + ni * 8 + 2 * lc) = make_float2(O[ni][0] * inv0, O[ni][1] * inv0);
        *(float2*)(y1 + ni * 8 + 2 * lc) = make_float2(O[ni][2] * inv1, O[ni][3] * inv1);
    }
}

// ---------------------------------------------------------------------------
// Launch. Inputs (metadata order): x, Wq, bq, Wk, bk, Wv, bv, Wp, bp
// ---------------------------------------------------------------------------
extern "C" void kernel_launch(void* const* d_in, const int* in_sizes, int n_in,
                              void* d_out, int out_size)
{
    (void)in_sizes; (void)n_in; (void)out_size;
    const float* x  = (const float*)d_in[0];
    const float* Wq = (const float*)d_in[1];
    const float* bq = (const float*)d_in[2];
    const float* Wk = (const float*)d_in[3];
    const float* bk = (const float*)d_in[4];
    const float* Wv = (const float*)d_in[5];
    const float* bv = (const float*)d_in[6];
    const float* Wp = (const float*)d_in[7];
    const float* bp = (const float*)d_in[8];
    float* out = (float*)d_out;

    cudaFuncSetAttribute(gemm_tf32, cudaFuncAttributeMaxDynamicSharedMemorySize,
                         GEMM_SMEM);
    cudaFuncSetAttribute(flash_attn_tc, cudaFuncAttributeMaxDynamicSharedMemorySize,
                         FA_SMEM);

    dim3 gemm_grid(D_ / 128, M_ / 128);   // (6, 64)
    dim3 gemm_block(256);

    gemm_tf32<<<gemm_grid, gemm_block, GEMM_SMEM>>>(x, Wq, bq, nullptr, 0);
    gemm_tf32<<<gemm_grid, gemm_block, GEMM_SMEM>>>(x, Wk, bk, nullptr, 1);
    gemm_tf32<<<gemm_grid, gemm_block, GEMM_SMEM>>>(x, Wv, bv, nullptr, 2);

    dim3 attn_grid(T_ / 128, B_ * H_);    // (16, 48)
    flash_attn_tc<<<attn_grid, 256, FA_SMEM>>>();

    gemm_tf32<<<gemm_grid, gemm_block, GEMM_SMEM>>>(nullptr, Wp, bp, out, 3);
}

// round 8
// speedup vs baseline: 4.0420x; 1.2315x over previous
#include <cuda_runtime.h>
#include <cstdint>

// Problem constants
#define B_   4
#define T_   2048
#define D_   768
#define H_   12
#define DH_  64
#define M_   (B_ * T_)     // 8192 rows

// Scratch (allocation-free: __device__ globals)
__device__ float g_q[B_ * H_ * T_ * DH_];   // [B,H,T,Dh]
__device__ float g_k[B_ * H_ * T_ * DH_];
__device__ float g_v[B_ * H_ * T_ * DH_];
__device__ float g_y[B_ * T_ * D_];         // [B,T,D] attention output

__device__ __forceinline__ uint32_t tf32_rna(float x) {
    uint32_t y;
    asm("cvt.rna.tf32.f32 %0, %1;" : "=r"(y) : "f"(x));
    return y;
}

__device__ __forceinline__ float ex2f(float x) {
    float y;
    asm("ex2.approx.f32 %0, %1;" : "=f"(y) : "f"(x));
    return y;
}

__device__ __forceinline__ void mma_tf32(float d[4], const uint32_t a[4],
                                         const uint32_t b[2]) {
    asm volatile(
        "mma.sync.aligned.m16n8k8.row.col.f32.tf32.tf32.f32 "
        "{%0,%1,%2,%3}, {%4,%5,%6,%7}, {%8,%9}, {%0,%1,%2,%3};"
        : "+f"(d[0]), "+f"(d[1]), "+f"(d[2]), "+f"(d[3])
        : "r"(a[0]), "r"(a[1]), "r"(a[2]), "r"(a[3]), "r"(b[0]), "r"(b[1]));
}

// ---------------------------------------------------------------------------
// TF32 mma.sync GEMM (unchanged — known good since R5).
// ---------------------------------------------------------------------------
#define KC        32
#define LDT       36
#define TILE_W    (128 * LDT)
#define BUF_W     (2 * TILE_W)
#define NITER     (D_ / KC)
#define GEMM_SMEM (2 * BUF_W * 4)

__global__ __launch_bounds__(256, 1) void gemm_tf32(
    const float* __restrict__ Aext, const float* __restrict__ W,
    const float* __restrict__ bias, float* __restrict__ outext, int mode)
{
    extern __shared__ uint32_t sm[];

    const int tid  = threadIdx.x;
    const int wid  = tid >> 5;
    const int lane = tid & 31;
    const int lr   = lane >> 2;
    const int lc   = lane & 3;
    const int warp_m = wid >> 2;
    const int warp_n = wid & 3;
    const int m0 = blockIdx.y * 128;
    const int n0 = blockIdx.x * 128;

    const float* A = (mode == 3) ? g_y : Aext;
    const float* Ap = A + (size_t)m0 * D_;
    const float* Wp = W + (size_t)n0 * D_;

    float d[4][4][4];
    #pragma unroll
    for (int mi = 0; mi < 4; mi++)
        #pragma unroll
        for (int ni = 0; ni < 4; ni++)
            #pragma unroll
            for (int r = 0; r < 4; r++) d[mi][ni][r] = 0.0f;

    float4 ra[4], rw[4];

    auto load_tile = [&](int it) {
        const int kk = it * KC;
        #pragma unroll
        for (int i = 0; i < 4; i++) {
            const int f   = tid + i * 256;
            const int row = f >> 3;
            const int c4  = f & 7;
            const size_t goff = (size_t)row * D_ + kk + c4 * 4;
            ra[i] = *(const float4*)(Ap + goff);
            rw[i] = *(const float4*)(Wp + goff);
        }
    };
    auto store_tile = [&](int b) {
        uint32_t* As = sm + b * BUF_W;
        uint32_t* Ws = As + TILE_W;
        #pragma unroll
        for (int i = 0; i < 4; i++) {
            const int f   = tid + i * 256;
            const int row = f >> 3;
            const int c4  = f & 7;
            const int off = row * LDT + c4 * 4;
            uint32_t a0 = tf32_rna(ra[i].x), a1 = tf32_rna(ra[i].y),
                     a2 = tf32_rna(ra[i].z), a3 = tf32_rna(ra[i].w);
            uint32_t w0 = tf32_rna(rw[i].x), w1 = tf32_rna(rw[i].y),
                     w2 = tf32_rna(rw[i].z), w3 = tf32_rna(rw[i].w);
            *(uint4*)(As + off) = make_uint4(a0, a1, a2, a3);
            *(uint4*)(Ws + off) = make_uint4(w0, w1, w2, w3);
        }
    };

    load_tile(0);
    store_tile(0);
    __syncthreads();

    for (int it = 0; it < NITER; ++it) {
        const int cur = it & 1;
        if (it + 1 < NITER) load_tile(it + 1);

        const uint32_t* As = sm + cur * BUF_W;
        const uint32_t* Ws = As + TILE_W;

        #pragma unroll
        for (int k0 = 0; k0 < KC; k0 += 8) {
            uint32_t a[4][4], b[4][2];
            #pragma unroll
            for (int mi = 0; mi < 4; mi++) {
                const int r = warp_m * 64 + mi * 16;
                a[mi][0] = As[(r + lr)     * LDT + k0 + lc];
                a[mi][1] = As[(r + 8 + lr) * LDT + k0 + lc];
                a[mi][2] = As[(r + lr)     * LDT + k0 + 4 + lc];
                a[mi][3] = As[(r + 8 + lr) * LDT + k0 + 4 + lc];
            }
            #pragma unroll
            for (int ni = 0; ni < 4; ni++) {
                const int n = warp_n * 32 + ni * 8;
                b[ni][0] = Ws[(n + lr) * LDT + k0 + lc];
                b[ni][1] = Ws[(n + lr) * LDT + k0 + 4 + lc];
            }
            #pragma unroll
            for (int mi = 0; mi < 4; mi++)
                #pragma unroll
                for (int ni = 0; ni < 4; ni++)
                    mma_tf32(d[mi][ni], a[mi], b[ni]);
        }

        if (it + 1 < NITER) store_tile(cur ^ 1);
        __syncthreads();
    }

    #pragma unroll
    for (int ni = 0; ni < 4; ni++) {
        const int c  = n0 + warp_n * 32 + ni * 8 + 2 * lc;
        const float b0 = __ldg(bias + c);
        const float b1 = __ldg(bias + c + 1);
        #pragma unroll
        for (int mi = 0; mi < 4; mi++) {
            #pragma unroll
            for (int half = 0; half < 2; half++) {
                const int m = m0 + warp_m * 64 + mi * 16 + half * 8 + lr;
                float2 r;
                r.x = d[mi][ni][half * 2 + 0] + b0;
                r.y = d[mi][ni][half * 2 + 1] + b1;
                float* op;
                if (mode == 3) {
                    op = outext + (size_t)m * D_ + c;
                } else {
                    const int bb = m / T_;
                    const int t  = m % T_;
                    const int h  = c / DH_;
                    const int dh = c % DH_;
                    float* base = (mode == 0) ? g_q : (mode == 1) ? g_k : g_v;
                    op = base + (((size_t)(bb * H_ + h)) * T_ + t) * DH_ + dh;
                }
                *(float2*)op = r;
            }
        }
    }
}

// ---------------------------------------------------------------------------
// Tensor-core causal flash attention, v3.
// Grid (T/128, B*H), block 256 (8 warps), 2 CTAs/SM. Warp w: query rows
// q0+16w..+15. KV tiles Bc=64. Plain tf32.
//
// Ks: rows (keys) permuted by psi within 8-groups; cols (dh) pair-interleaved
//     -> S fragments read as single LDS.64 AND S accumulator physical col c
//        holds logical key kappa(c): {c0,c2,c1,c3} IS the PV A-fragment.
//        P never touches smem.
// Vs: natural row-major [key][dh] (conflict-free STS.128 store);
//     PV B-frags = 2 conflict-free LDS.32.
// smem: Ks[64][72] + Vs[64][72] = 36,864 B.
// ---------------------------------------------------------------------------
#define FA_LD    72
#define FA_KS_W  (64 * FA_LD)
#define FA_SMEM  (2 * FA_KS_W * 4)
#define CEXP     0.1803368801111244f      // 0.125 * log2(e)

__global__ __launch_bounds__(256, 2) void flash_attn_tc()
{
    extern __shared__ uint32_t fsm[];
    uint32_t* Ks = fsm;                   // keys psi-permuted, dh interleaved
    uint32_t* Vs = fsm + FA_KS_W;         // [key][dh] natural

    const int tid  = threadIdx.x;
    const int wid  = tid >> 5;
    const int lane = tid & 31;
    const int lr   = lane >> 2;           // 0..7
    const int lc   = lane & 3;            // 0..3

    const int bh = blockIdx.y;
    const int q0 = blockIdx.x * 128;
    const int qr0 = q0 + wid * 16;
    const int r0 = qr0 + lr;
    const int r1 = r0 + 8;

    const float* Qb = g_q + (size_t)bh * T_ * DH_;
    const float* Kb = g_k + (size_t)bh * T_ * DH_;
    const float* Vb = g_v + (size_t)bh * T_ * DH_;

    // Q a-fragments (plain tf32)
    uint32_t q[8][4];
    #pragma unroll
    for (int ks = 0; ks < 8; ks++) {
        q[ks][0] = tf32_rna(Qb[(size_t)r0 * DH_ + ks * 8 + lc]);
        q[ks][1] = tf32_rna(Qb[(size_t)r1 * DH_ + ks * 8 + lc]);
        q[ks][2] = tf32_rna(Qb[(size_t)r0 * DH_ + ks * 8 + lc + 4]);
        q[ks][3] = tf32_rna(Qb[(size_t)r1 * DH_ + ks * 8 + lc + 4]);
    }

    float O[8][4];
    #pragma unroll
    for (int ni = 0; ni < 8; ni++)
        #pragma unroll
        for (int r = 0; r < 4; r++) O[ni][r] = 0.0f;

    float m0r = -1e30f, m1r = -1e30f;
    float l0 = 0.0f, l1 = 0.0f;

    // PV V base pointers (B-frag k rows: keys 8ks+lc and 8ks+lc+4)
    const uint32_t* vb0 = Vs + lc * FA_LD + lr;
    const uint32_t* vb1 = Vs + (lc + 4) * FA_LD + lr;

    const int jend = q0 + 128;
    for (int j0 = 0; j0 < jend; j0 += 64) {
        // ---- cooperative K/V tile load ----
        __syncthreads();
        {
            const float* Kg = Kb + (size_t)j0 * DH_;
            const float* Vg = Vb + (size_t)j0 * DH_;
            #pragma unroll
            for (int i = 0; i < 4; i++) {
                const int f   = tid + i * 256;      // 0..1023 float4 slots
                const int row = f >> 4;             // key 0..63
                const int c4  = f & 15;             // float4 dh col
                // K: row permuted by psi, dh cols pair-interleaved
                float4 kv = *(const float4*)(Kg + row * DH_ + c4 * 4);
                const int rowp = (row & 56) | (((row & 3) << 1) | ((row & 7) >> 2));
                uint32_t* kb = Ks + rowp * FA_LD + (c4 >> 1) * 8 + (c4 & 1);
                kb[0] = tf32_rna(kv.x);
                kb[2] = tf32_rna(kv.y);
                kb[4] = tf32_rna(kv.z);
                kb[6] = tf32_rna(kv.w);
                // V: natural [key][dh], tf32-rounded, one STS.128
                float4 vv = *(const float4*)(Vg + row * DH_ + c4 * 4);
                *(uint4*)(Vs + row * FA_LD + c4 * 4) =
                    make_uint4(tf32_rna(vv.x), tf32_rna(vv.y),
                               tf32_rna(vv.z), tf32_rna(vv.w));
            }
        }
        __syncthreads();

        if (j0 > qr0 + 15) continue;      // whole warp-tile above diagonal

        // ---- S = Q @ K^T  (phys col c <-> logical key kappa(c)) ----
        float S[8][4];
        #pragma unroll
        for (int ni = 0; ni < 8; ni++) {
            S[ni][0] = S[ni][1] = S[ni][2] = S[ni][3] = 0.0f;
            #pragma unroll
            for (int ks = 0; ks < 8; ks++) {
                uint2 bv = *(const uint2*)(Ks + (ni * 8 + lr) * FA_LD
                                              + ks * 8 + 2 * lc);
                uint32_t b2[2] = { bv.x, bv.y };
                mma_tf32(S[ni], q[ks], b2);
            }
        }

        // ---- causal mask: c0/c2 -> key j0+8ni+lc, c1/c3 -> +lc+4 ----
        if (j0 + 63 > qr0) {
            #pragma unroll
            for (int ni = 0; ni < 8; ni++) {
                const int ka = j0 + ni * 8 + lc;
                const int kb2 = ka + 4;
                if (ka  > r0) S[ni][0] = -1e30f;
                if (kb2 > r0) S[ni][1] = -1e30f;
                if (ka  > r1) S[ni][2] = -1e30f;
                if (kb2 > r1) S[ni][3] = -1e30f;
            }
        }

        // ---- online softmax ----
        float m0n = m0r, m1n = m1r;
        #pragma unroll
        for (int ni = 0; ni < 8; ni++) {
            m0n = fmaxf(m0n, fmaxf(S[ni][0], S[ni][1]));
            m1n = fmaxf(m1n, fmaxf(S[ni][2], S[ni][3]));
        }
        m0n = fmaxf(m0n, __shfl_xor_sync(0xFFFFFFFFu, m0n, 1));
        m0n = fmaxf(m0n, __shfl_xor_sync(0xFFFFFFFFu, m0n, 2));
        m1n = fmaxf(m1n, __shfl_xor_sync(0xFFFFFFFFu, m1n, 1));
        m1n = fmaxf(m1n, __shfl_xor_sync(0xFFFFFFFFu, m1n, 2));

        const float sf0 = ex2f((m0r - m0n) * CEXP);
        const float sf1 = ex2f((m1r - m1n) * CEXP);
        m0r = m0n; m1r = m1n;
        l0 *= sf0; l1 *= sf1;
        #pragma unroll
        for (int ni = 0; ni < 8; ni++) {
            O[ni][0] *= sf0; O[ni][1] *= sf0;
            O[ni][2] *= sf1; O[ni][3] *= sf1;
        }

        // ---- P = exp(S - m), still in registers ----
        const float mc0 = m0n * CEXP;
        const float mc1 = m1n * CEXP;
        #pragma unroll
        for (int ni = 0; ni < 8; ni++) {
            S[ni][0] = ex2f(fmaf(S[ni][0], CEXP, -mc0));
            S[ni][1] = ex2f(fmaf(S[ni][1], CEXP, -mc0));
            S[ni][2] = ex2f(fmaf(S[ni][2], CEXP, -mc1));
            S[ni][3] = ex2f(fmaf(S[ni][3], CEXP, -mc1));
            l0 += S[ni][0] + S[ni][1];
            l1 += S[ni][2] + S[ni][3];
        }

        // ---- O += P @ V : A-frag = {c0, c2, c1, c3} of S, B from Vs ----
        #pragma unroll
        for (int ks = 0; ks < 8; ks++) {
            uint32_t a[4] = { tf32_rna(S[ks][0]), tf32_rna(S[ks][2]),
                              tf32_rna(S[ks][1]), tf32_rna(S[ks][3]) };
            #pragma unroll
            for (int ni = 0; ni < 8; ni++) {
                uint32_t b2[2] = { vb0[ks * 8 * FA_LD + ni * 8],
                                   vb1[ks * 8 * FA_LD + ni * 8] };
                mma_tf32(O[ni], a, b2);
            }
        }
    }

    // ---- finalize ----
    l0 += __shfl_xor_sync(0xFFFFFFFFu, l0, 1);
    l0 += __shfl_xor_sync(0xFFFFFFFFu, l0, 2);
    l1 += __shfl_xor_sync(0xFFFFFFFFu, l1, 1);
    l1 += __shfl_xor_sync(0xFFFFFFFFu, l1, 2);
    const float inv0 = 1.0f / l0;
    const float inv1 = 1.0f / l1;

    const int b = bh / H_;
    const int h = bh % H_;
    float* y0 = g_y + ((size_t)(b * T_ + r0)) * D_ + h * DH_;
    float* y1 = g_y + ((size_t)(b * T_ + r1)) * D_ + h * DH_;
    #pragma unroll
    for (int ni = 0; ni < 8; ni++) {
        *(float2*)(y0 + ni * 8 + 2 * lc) = make_float2(O[ni][0] * inv0, O[ni][1] * inv0);
        *(float2*)(y1 + ni * 8 + 2 * lc) = make_float2(O[ni][2] * inv1, O[ni][3] * inv1);
    }
}

// ---------------------------------------------------------------------------
// Launch. Inputs (metadata order): x, Wq, bq, Wk, bk, Wv, bv, Wp, bp
// ---------------------------------------------------------------------------
extern "C" void kernel_launch(void* const* d_in, const int* in_sizes, int n_in,
                              void* d_out, int out_size)
{
    (void)in_sizes; (void)n_in; (void)out_size;
    const float* x  = (const float*)d_in[0];
    const float* Wq = (const float*)d_in[1];
    const float* bq = (const float*)d_in[2];
    const float* Wk = (const float*)d_in[3];
    const float* bk = (const float*)d_in[4];
    const float* Wv = (const float*)d_in[5];
    const float* bv = (const float*)d_in[6];
    const float* Wp = (const float*)d_in[7];
    const float* bp = (const float*)d_in[8];
    float* out = (float*)d_out;

    cudaFuncSetAttribute(gemm_tf32, cudaFuncAttributeMaxDynamicSharedMemorySize,
                         GEMM_SMEM);
    cudaFuncSetAttribute(flash_attn_tc, cudaFuncAttributeMaxDynamicSharedMemorySize,
                         FA_SMEM);

    dim3 gemm_grid(D_ / 128, M_ / 128);   // (6, 64)
    dim3 gemm_block(256);

    gemm_tf32<<<gemm_grid, gemm_block, GEMM_SMEM>>>(x, Wq, bq, nullptr, 0);
    gemm_tf32<<<gemm_grid, gemm_block, GEMM_SMEM>>>(x, Wk, bk, nullptr, 1);
    gemm_tf32<<<gemm_grid, gemm_block, GEMM_SMEM>>>(x, Wv, bv, nullptr, 2);

    dim3 attn_grid(T_ / 128, B_ * H_);    // (16, 48)
    flash_attn_tc<<<attn_grid, 256, FA_SMEM>>>();

    gemm_tf32<<<gemm_grid, gemm_block, GEMM_SMEM>>>(nullptr, Wp, bp, out, 3);
}